// round 7
// baseline (speedup 1.0000x reference)
#include <cuda_runtime.h>
#include <cuda_bf16.h>
#include <cstdint>

#define N_NODES   200000
#define N_EDGES   400000
#define IN_CH     768
#define HID_CH    256
#define NUM_GRAPHS 8000

// ---------------- scratch (device globals: no allocations allowed) ----------
__device__ int   g_is64;
__device__ int   g_total;
__device__ int   g_edges[2 * N_EDGES];          // [src(E), dst(E)] as int32
__device__ int   g_batch[N_NODES];
__device__ int   g_indeg[N_NODES];
__device__ int   g_rowbeg[N_NODES];             // CSR range start (arbitrary order)
__device__ int   g_cursor[N_NODES];
__device__ int   g_csrc[N_EDGES];               // CSR-by-dst: src ids
__device__ float g_dinv[N_NODES];               // rsqrt(1 + indeg)
__device__ float g_h[(size_t)N_NODES * 256];    // GEMM output (pre-agg features)
__device__ float g_a[(size_t)N_NODES * 256];    // aggregated output
__device__ __nv_bfloat16 g_w1hi[256 * IN_CH];   // W^T hi/lo splits, [n][k] K-major
__device__ __nv_bfloat16 g_w1lo[256 * IN_CH];
__device__ __nv_bfloat16 g_w2hi[256 * HID_CH];
__device__ __nv_bfloat16 g_w2lo[256 * HID_CH];

// ---------------- setup ------------------------------------------------------
__global__ void k_detect(const int* ei32) {
    __shared__ int any;
    if (threadIdx.x == 0) any = 0;
    __syncthreads();
    int idx = threadIdx.x * 3120 + 1;           // max 795601 < 800000 (safe if int32)
    if (ei32[idx] != 0) any = 1;
    __syncthreads();
    if (threadIdx.x == 0) { g_is64 = (any == 0) ? 1 : 0; g_total = 0; }
}

__global__ void k_wprep(const float* __restrict__ W1, const float* __restrict__ W2) {
    int i = blockIdx.x * blockDim.x + threadIdx.x;
    if (i < N_NODES) g_indeg[i] = 0;
    if (i < IN_CH * 256) {
        int k = i / 256, n = i % 256;
        float w = W1[i];
        __nv_bfloat16 h = __float2bfloat16_rn(w);
        g_w1hi[(size_t)n * IN_CH + k] = h;
        g_w1lo[(size_t)n * IN_CH + k] = __float2bfloat16_rn(w - __bfloat162float(h));
    } else {
        int j = i - IN_CH * 256;
        if (j < HID_CH * 256) {
            int k = j / 256, n = j % 256;
            float w = W2[j];
            __nv_bfloat16 h = __float2bfloat16_rn(w);
            g_w2hi[(size_t)n * HID_CH + k] = h;
            g_w2lo[(size_t)n * HID_CH + k] = __float2bfloat16_rn(w - __bfloat162float(h));
        }
    }
}

__global__ void k_convert_deg(const void* ei, const void* bat) {
    int i = blockIdx.x * blockDim.x + threadIdx.x;
    bool is64 = (g_is64 != 0);
    if (i < N_NODES) {
        g_batch[i] = is64 ? (int)((const long long*)bat)[i] : ((const int*)bat)[i];
    }
    if (i < 2 * N_EDGES) {
        int v = is64 ? (int)((const long long*)ei)[i] : ((const int*)ei)[i];
        g_edges[i] = v;
        if (i >= N_EDGES) atomicAdd(&g_indeg[v], 1);   // dst half
    }
}

__global__ void k_alloc() {
    int i = blockIdx.x * blockDim.x + threadIdx.x;
    if (i >= N_NODES) return;
    int d = g_indeg[i];
    int beg = atomicAdd(&g_total, d);           // uniform-addr -> REDUX aggregated
    g_rowbeg[i] = beg;
    g_cursor[i] = beg;
    g_dinv[i] = rsqrtf(1.0f + (float)d);
}

__global__ void k_fill() {
    int e = blockIdx.x * blockDim.x + threadIdx.x;
    if (e < N_EDGES) {
        int s = g_edges[e], d = g_edges[N_EDGES + e];
        int pos = atomicAdd(&g_cursor[d], 1);
        g_csrc[pos] = s;
    }
}

// ---------------- GEMM helpers ------------------------------------------------
__device__ __forceinline__ void ldsm4(uint32_t r[4], uint32_t addr) {
    asm volatile("ldmatrix.sync.aligned.m8n8.x4.shared.b16 {%0,%1,%2,%3}, [%4];"
        : "=r"(r[0]), "=r"(r[1]), "=r"(r[2]), "=r"(r[3]) : "r"(addr));
}
__device__ __forceinline__ void mma16816(float c[4], const uint32_t a[4], const uint32_t b[2]) {
    asm volatile(
        "mma.sync.aligned.m16n8k16.row.col.f32.bf16.bf16.f32 "
        "{%0,%1,%2,%3}, {%4,%5,%6,%7}, {%8,%9}, {%0,%1,%2,%3};"
        : "+f"(c[0]), "+f"(c[1]), "+f"(c[2]), "+f"(c[3])
        : "r"(a[0]), "r"(a[1]), "r"(a[2]), "r"(a[3]), "r"(b[0]), "r"(b[1]));
}
__device__ __forceinline__ void cpasync16(uint32_t dst, const void* src) {
    asm volatile("cp.async.cg.shared.global [%0], [%1], 16;" :: "r"(dst), "l"(src));
}
__device__ __forceinline__ uint32_t smem_u32(const void* p) {
    uint32_t a;
    asm("{ .reg .u64 t; cvta.to.shared.u64 t, %1; cvt.u32.u64 %0, t; }" : "=r"(a) : "l"(p));
    return a;
}

// BM=128, BN=256, BK=32, 512 threads (16 warps: 4M x 4N), warp tile 32x64.
// 3-stage cp.async pipeline (wait_group 1). Rows padded to 40 bf16 (80B).
#define BKP 40
#define OFF_AHI 0
#define OFF_ALO (128 * BKP * 2)                  // 10240
#define OFF_BHI (2 * 128 * BKP * 2)              // 20480
#define OFF_BLO (OFF_BHI + 256 * BKP * 2)        // 40960
#define ST_BYTES (OFF_BLO + 256 * BKP * 2)       // 61440
#define N_STAGE 3
#define SMEM_DYN (N_STAGE * ST_BYTES)            // 184320

template<int K, bool FUSE>
__global__ __launch_bounds__(512, 1) void k_gemm_tc(
    const float* __restrict__ A,
    const __nv_bfloat16* __restrict__ BHi, const __nv_bfloat16* __restrict__ BLo,
    const float* __restrict__ bias, float* __restrict__ H, int M)
{
    extern __shared__ __align__(16) char smem[];
    const uint32_t sb = smem_u32(smem);

    const int tid  = threadIdx.x;
    const int lane = tid & 31;
    const int wid  = tid >> 5;
    const int bm   = blockIdx.x * 128;
    const int wm   = (wid & 3) * 32;
    const int wn   = (wid >> 2) * 64;

    // A loader: row = tid>>2 (0..127), quarter = tid&3 (8 floats each)
    const int aRow = tid >> 2;
    const int aQ   = tid & 3;
    const bool aValid = (bm + aRow) < M;
    const float* Ap = A + (size_t)(bm + aRow) * K + aQ * 8;
    const uint32_t aStsOff = (uint32_t)aRow * (BKP * 2) + aQ * 16;

    // B loader: chunk q = tid + 512*i -> row q>>2 (0..255), u = q&3 (16B)
    const int bRow0 = tid >> 2;
    const int bU    = tid & 3;

    // ldmatrix per-lane addresses
    const uint32_t aOff = (uint32_t)(wm + (lane & 15)) * (BKP * 2) + ((lane >> 4) << 4);
    const uint32_t bOff = (uint32_t)(wn + (lane & 7) + ((lane >> 4) & 1) * 8) * (BKP * 2)
                        + (((lane >> 3) & 1) << 4);

    float acc[2][8][4];
    #pragma unroll
    for (int mt = 0; mt < 2; mt++)
        #pragma unroll
        for (int nt = 0; nt < 8; nt++)
            #pragma unroll
            for (int j = 0; j < 4; j++) acc[mt][nt][j] = 0.0f;

    constexpr int KT = K / 32;

    float4 aReg[2];
    auto loadA = [&](int kt) {
        #pragma unroll
        for (int i = 0; i < 2; i++) {
            float4 t = aValid ? *(const float4*)(Ap + kt * 32 + 4 * i)
                              : make_float4(0.f, 0.f, 0.f, 0.f);
            if constexpr (FUSE) {
                float4 bb = *(const float4*)(bias + kt * 32 + aQ * 8 + 4 * i);
                t.x = fmaxf(t.x + bb.x, 0.f); t.y = fmaxf(t.y + bb.y, 0.f);
                t.z = fmaxf(t.z + bb.z, 0.f); t.w = fmaxf(t.w + bb.w, 0.f);
                if (!aValid) t = make_float4(0.f, 0.f, 0.f, 0.f);
            }
            aReg[i] = t;
        }
    };
    auto stsA = [&](uint32_t stage) {
        uint32_t hw[4], lw[4];
        #pragma unroll
        for (int i = 0; i < 2; i++) {
            float4 v = aReg[i];
            __nv_bfloat16 b0 = __float2bfloat16_rn(v.x);
            __nv_bfloat16 b1 = __float2bfloat16_rn(v.y);
            __nv_bfloat16 b2 = __float2bfloat16_rn(v.z);
            __nv_bfloat16 b3 = __float2bfloat16_rn(v.w);
            __nv_bfloat162 h0; h0.x = b0; h0.y = b1;
            __nv_bfloat162 h1; h1.x = b2; h1.y = b3;
            __nv_bfloat162 l0;
            l0.x = __float2bfloat16_rn(v.x - __bfloat162float(b0));
            l0.y = __float2bfloat16_rn(v.y - __bfloat162float(b1));
            __nv_bfloat162 l1;
            l1.x = __float2bfloat16_rn(v.z - __bfloat162float(b2));
            l1.y = __float2bfloat16_rn(v.w - __bfloat162float(b3));
            hw[2 * i] = *(uint32_t*)&h0; hw[2 * i + 1] = *(uint32_t*)&h1;
            lw[2 * i] = *(uint32_t*)&l0; lw[2 * i + 1] = *(uint32_t*)&l1;
        }
        uint32_t d = stage + OFF_AHI + aStsOff;
        asm volatile("st.shared.v4.b32 [%0], {%1,%2,%3,%4};"
                     :: "r"(d), "r"(hw[0]), "r"(hw[1]), "r"(hw[2]), "r"(hw[3]) : "memory");
        d = stage + OFF_ALO + aStsOff;
        asm volatile("st.shared.v4.b32 [%0], {%1,%2,%3,%4};"
                     :: "r"(d), "r"(lw[0]), "r"(lw[1]), "r"(lw[2]), "r"(lw[3]) : "memory");
    };
    auto cpB = [&](int kt, uint32_t stage) {
        #pragma unroll
        for (int i = 0; i < 2; i++) {
            int row = bRow0 + i * 128;           // 0..255
            uint32_t off = (uint32_t)row * (BKP * 2) + bU * 16;
            const __nv_bfloat16* srcH = BHi + (size_t)row * K + kt * 32 + bU * 8;
            const __nv_bfloat16* srcL = BLo + (size_t)row * K + kt * 32 + bU * 8;
            cpasync16(stage + OFF_BHI + off, srcH);
            cpasync16(stage + OFF_BLO + off, srcL);
        }
        asm volatile("cp.async.commit_group;" ::: "memory");
    };

    // prologue: fill stages 0 and 1
    loadA(0); stsA(sb);
    cpB(0, sb);
    loadA(1); stsA(sb + ST_BYTES);
    cpB(1, sb + ST_BYTES);

    for (int kt = 0; kt < KT; kt++) {
        const uint32_t cur = sb + (kt % N_STAGE) * ST_BYTES;
        const uint32_t nxt2 = sb + ((kt + 2) % N_STAGE) * ST_BYTES;

        if (kt + 1 < KT)
            asm volatile("cp.async.wait_group 1;" ::: "memory");
        else
            asm volatile("cp.async.wait_group 0;" ::: "memory");
        __syncthreads();

        if (kt + 2 < KT) loadA(kt + 2);          // LDG in flight under the mma loop

        #pragma unroll
        for (int kk = 0; kk < 2; kk++) {
            const uint32_t ko = kk * 32;
            uint32_t afh[2][4], afl[2][4];
            #pragma unroll
            for (int mt = 0; mt < 2; mt++) {
                ldsm4(afh[mt], cur + OFF_AHI + aOff + mt * (16 * BKP * 2) + ko);
                ldsm4(afl[mt], cur + OFF_ALO + aOff + mt * (16 * BKP * 2) + ko);
            }
            #pragma unroll
            for (int np = 0; np < 4; np++) {
                uint32_t bfh[4], bfl[4];
                ldsm4(bfh, cur + OFF_BHI + bOff + np * (16 * BKP * 2) + ko);
                ldsm4(bfl, cur + OFF_BLO + bOff + np * (16 * BKP * 2) + ko);
                #pragma unroll
                for (int mt = 0; mt < 2; mt++)
                    #pragma unroll
                    for (int j = 0; j < 2; j++) {
                        const int nt = np * 2 + j;
                        mma16816(acc[mt][nt], afh[mt], &bfh[j * 2]);
                        mma16816(acc[mt][nt], afh[mt], &bfl[j * 2]);
                        mma16816(acc[mt][nt], afl[mt], &bfh[j * 2]);
                    }
            }
        }

        if (kt + 2 < KT) {
            stsA(nxt2);                          // stage freed at iter kt-1
            cpB(kt + 2, nxt2);
        }
    }

    // epilogue
    #pragma unroll
    for (int mt = 0; mt < 2; mt++) {
        int r0 = bm + wm + mt * 16 + (lane >> 2);
        int r1 = r0 + 8;
        #pragma unroll
        for (int nt = 0; nt < 8; nt++) {
            int cn = wn + nt * 8 + (lane & 3) * 2;
            if (r0 < M)
                *(float2*)&H[(size_t)r0 * 256 + cn] = make_float2(acc[mt][nt][0], acc[mt][nt][1]);
            if (r1 < M)
                *(float2*)&H[(size_t)r1 * 256 + cn] = make_float2(acc[mt][nt][2], acc[mt][nt][3]);
        }
    }
}

// ---------------- CSR aggregation: warp per dst row, no atomics --------------
__global__ __launch_bounds__(256) void k_agg_csr(const float* __restrict__ h,
                                                 float* __restrict__ a) {
    int r = blockIdx.x * 8 + (threadIdx.x >> 5);
    if (r >= N_NODES) return;
    int lane = threadIdx.x & 31;
    float dr = g_dinv[r];
    float w0 = dr * dr;
    const float4* hr = (const float4*)(h + (size_t)r * 256);
    float4 v0 = hr[lane], v1 = hr[lane + 32];
    float4 a0 = make_float4(v0.x * w0, v0.y * w0, v0.z * w0, v0.w * w0);
    float4 a1 = make_float4(v1.x * w0, v1.y * w0, v1.z * w0, v1.w * w0);
    int beg = g_rowbeg[r], end = beg + g_indeg[r];
    for (int t = beg; t < end; t++) {
        int s = g_csrc[t];
        float w = g_dinv[s] * dr;
        const float4* hs = (const float4*)(h + (size_t)s * 256);
        float4 u0 = hs[lane], u1 = hs[lane + 32];
        a0.x += u0.x * w; a0.y += u0.y * w; a0.z += u0.z * w; a0.w += u0.w * w;
        a1.x += u1.x * w; a1.y += u1.y * w; a1.z += u1.z * w; a1.w += u1.w * w;
    }
    float4* ar = (float4*)(a + (size_t)r * 256);
    ar[lane] = a0;
    ar[lane + 32] = a1;
}

// ---------------- pooling: batch sorted -> binary search per graph -----------
__global__ void k_pool(const float* __restrict__ a, const float* __restrict__ b2,
                       float* __restrict__ out) {
    int g = blockIdx.x;
    __shared__ int sLo, sHi;
    if (threadIdx.x == 0) {
        int lo = 0, hi = N_NODES;
        while (lo < hi) { int mid = (lo + hi) >> 1; if (g_batch[mid] < g) lo = mid + 1; else hi = mid; }
        sLo = lo;
        hi = N_NODES;
        while (lo < hi) { int mid = (lo + hi) >> 1; if (g_batch[mid] < g + 1) lo = mid + 1; else hi = mid; }
        sHi = lo;
    }
    __syncthreads();
    int c = threadIdx.x;
    float sum = 0.0f;
    for (int v = sLo; v < sHi; v++) sum += a[(size_t)v * 256 + c];
    int cnt = sHi - sLo;
    out[(size_t)g * 256 + c] = (cnt > 0) ? (sum / (float)cnt + b2[c]) : 0.0f;
}

// ---------------- launcher ---------------------------------------------------
extern "C" void kernel_launch(void* const* d_in, const int* in_sizes, int n_in,
                              void* d_out, int out_size) {
    const float* x    = (const float*)d_in[0];
    const float* W1   = (const float*)d_in[1];
    const float* b1   = (const float*)d_in[2];
    const float* W2   = (const float*)d_in[3];
    const float* b2   = (const float*)d_in[4];
    const void*  ei   = d_in[5];
    const void*  bat  = d_in[6];
    float* out = (float*)d_out;

    float *ph, *pa;
    __nv_bfloat16 *pw1h, *pw1l, *pw2h, *pw2l;
    cudaGetSymbolAddress((void**)&ph, g_h);
    cudaGetSymbolAddress((void**)&pa, g_a);
    cudaGetSymbolAddress((void**)&pw1h, g_w1hi);
    cudaGetSymbolAddress((void**)&pw1l, g_w1lo);
    cudaGetSymbolAddress((void**)&pw2h, g_w2hi);
    cudaGetSymbolAddress((void**)&pw2l, g_w2lo);

    cudaFuncSetAttribute(k_gemm_tc<IN_CH, false>,
                         cudaFuncAttributeMaxDynamicSharedMemorySize, SMEM_DYN);
    cudaFuncSetAttribute(k_gemm_tc<HID_CH, true>,
                         cudaFuncAttributeMaxDynamicSharedMemorySize, SMEM_DYN);

    const int nGemmBlk = (N_NODES + 127) / 128;  // 1563

    // launch index 3 = GEMM1 (ncu profiles launch index 3)
    k_detect<<<1, 256>>>((const int*)ei);                                 // 0
    k_wprep<<<((IN_CH + HID_CH) * 256 + 255) / 256, 256>>>(W1, W2);       // 1 (zeros indeg too)
    k_convert_deg<<<(2 * N_EDGES + 255) / 256, 256>>>(ei, bat);           // 2
    k_gemm_tc<IN_CH, false><<<nGemmBlk, 512, SMEM_DYN>>>(                 // 3 <- profiled
        x, pw1h, pw1l, nullptr, ph, N_NODES);
    k_alloc<<<(N_NODES + 255) / 256, 256>>>();                            // 4
    k_fill<<<(N_EDGES + 255) / 256, 256>>>();                             // 5
    k_agg_csr<<<(N_NODES + 7) / 8, 256>>>(ph, pa);                        // 6
    k_gemm_tc<HID_CH, true><<<nGemmBlk, 512, SMEM_DYN>>>(                 // 7
        pa, pw2h, pw2l, b1, ph, N_NODES);
    k_agg_csr<<<(N_NODES + 7) / 8, 256>>>(ph, pa);                        // 8
    k_pool<<<NUM_GRAPHS, 256>>>(pa, b2, out);                             // 9
}

// round 8
// speedup vs baseline: 1.8981x; 1.8981x over previous
#include <cuda_runtime.h>
#include <cuda_fp16.h>
#include <cstdint>

#define N_NODES   200000
#define N_EDGES   400000
#define IN_CH     768
#define HID_CH    256
#define NUM_GRAPHS 8000

// ---------------- scratch (device globals: no allocations allowed) ----------
__device__ int   g_is64;
__device__ int   g_total;
__device__ int   g_edges[2 * N_EDGES];          // [src(E), dst(E)] as int32
__device__ int   g_batch[N_NODES];
__device__ int   g_indeg[N_NODES];
__device__ int   g_rowbeg[N_NODES];             // CSR range start (arbitrary order)
__device__ int   g_cursor[N_NODES];
__device__ int   g_csrc[N_EDGES];               // CSR-by-dst: src ids
__device__ float g_dinv[N_NODES];               // rsqrt(1 + indeg)
__device__ float g_h[(size_t)N_NODES * 256];    // GEMM output (pre-agg features)
__device__ float g_a[(size_t)N_NODES * 256];    // aggregated output
__device__ __half g_w1hi[256 * IN_CH];          // W^T fp16 hi/lo splits, [n][k] K-major
__device__ __half g_w1lo[256 * IN_CH];
__device__ __half g_w2hi[256 * HID_CH];
__device__ __half g_w2lo[256 * HID_CH];

// ---------------- setup ------------------------------------------------------
__global__ void k_detect(const int* ei32) {
    __shared__ int any;
    if (threadIdx.x == 0) any = 0;
    __syncthreads();
    int idx = threadIdx.x * 3120 + 1;           // max 795601 < 800000 (safe if int32)
    if (ei32[idx] != 0) any = 1;
    __syncthreads();
    if (threadIdx.x == 0) { g_is64 = (any == 0) ? 1 : 0; g_total = 0; }
}

__global__ void k_wprep(const float* __restrict__ W1, const float* __restrict__ W2) {
    int i = blockIdx.x * blockDim.x + threadIdx.x;
    if (i < N_NODES) g_indeg[i] = 0;
    if (i < IN_CH * 256) {
        int k = i / 256, n = i % 256;
        float w = W1[i];
        __half h = __float2half_rn(w);
        g_w1hi[(size_t)n * IN_CH + k] = h;
        g_w1lo[(size_t)n * IN_CH + k] = __float2half_rn(w - __half2float(h));
    } else {
        int j = i - IN_CH * 256;
        if (j < HID_CH * 256) {
            int k = j / 256, n = j % 256;
            float w = W2[j];
            __half h = __float2half_rn(w);
            g_w2hi[(size_t)n * HID_CH + k] = h;
            g_w2lo[(size_t)n * HID_CH + k] = __float2half_rn(w - __half2float(h));
        }
    }
}

__global__ void k_convert_deg(const void* ei, const void* bat) {
    int i = blockIdx.x * blockDim.x + threadIdx.x;
    bool is64 = (g_is64 != 0);
    if (i < N_NODES) {
        g_batch[i] = is64 ? (int)((const long long*)bat)[i] : ((const int*)bat)[i];
    }
    if (i < 2 * N_EDGES) {
        int v = is64 ? (int)((const long long*)ei)[i] : ((const int*)ei)[i];
        g_edges[i] = v;
        if (i >= N_EDGES) atomicAdd(&g_indeg[v], 1);   // dst half
    }
}

__global__ void k_alloc() {
    int i = blockIdx.x * blockDim.x + threadIdx.x;
    if (i >= N_NODES) return;
    int d = g_indeg[i];
    int beg = atomicAdd(&g_total, d);           // uniform-addr -> REDUX aggregated
    g_rowbeg[i] = beg;
    g_cursor[i] = beg;
    g_dinv[i] = rsqrtf(1.0f + (float)d);
}

__global__ void k_fill() {
    int e = blockIdx.x * blockDim.x + threadIdx.x;
    if (e < N_EDGES) {
        int s = g_edges[e], d = g_edges[N_EDGES + e];
        int pos = atomicAdd(&g_cursor[d], 1);
        g_csrc[pos] = s;
    }
}

// ---------------- GEMM helpers ------------------------------------------------
__device__ __forceinline__ void ldsm4(uint32_t r[4], uint32_t addr) {
    asm volatile("ldmatrix.sync.aligned.m8n8.x4.shared.b16 {%0,%1,%2,%3}, [%4];"
        : "=r"(r[0]), "=r"(r[1]), "=r"(r[2]), "=r"(r[3]) : "r"(addr));
}
__device__ __forceinline__ void mma16816(float c[4], const uint32_t a[4], const uint32_t b[2]) {
    asm volatile(
        "mma.sync.aligned.m16n8k16.row.col.f32.f16.f16.f32 "
        "{%0,%1,%2,%3}, {%4,%5,%6,%7}, {%8,%9}, {%0,%1,%2,%3};"
        : "+f"(c[0]), "+f"(c[1]), "+f"(c[2]), "+f"(c[3])
        : "r"(a[0]), "r"(a[1]), "r"(a[2]), "r"(a[3]), "r"(b[0]), "r"(b[1]));
}
__device__ __forceinline__ void cpasync16(uint32_t dst, const void* src) {
    asm volatile("cp.async.cg.shared.global [%0], [%1], 16;" :: "r"(dst), "l"(src));
}
__device__ __forceinline__ uint32_t smem_u32(const void* p) {
    uint32_t a;
    asm("{ .reg .u64 t; cvta.to.shared.u64 t, %1; cvt.u32.u64 %0, t; }" : "=r"(a) : "l"(p));
    return a;
}

// BM=128, BN=128, BK=32, 256 threads (8 warps: 4M x 2N), 2-stage, 2 CTAs/SM.
// A: single fp16 (rounded). B: fp16 hi+lo split -> 2 mma products.
#define BKP 40                       // padded BK row (fp16): 80B stride
#define OFF_AHI 0
#define OFF_BHI (128 * BKP * 2)      // 10240
#define OFF_BLO (2 * 128 * BKP * 2)  // 20480
#define ST_BYTES (3 * 128 * BKP * 2) // 30720 per stage
#define SMEM_DYN (2 * ST_BYTES)      // 61440 (2 CTAs = 120KB <= 228KB)

template<int K, bool FUSE>
__global__ __launch_bounds__(256, 2) void k_gemm_tc(
    const float* __restrict__ A,
    const __half* __restrict__ BHi, const __half* __restrict__ BLo,
    const float* __restrict__ bias, float* __restrict__ H, int M)
{
    extern __shared__ __align__(16) char smem[];
    const uint32_t sb = smem_u32(smem);

    const int tid  = threadIdx.x;
    const int lane = tid & 31;
    const int wid  = tid >> 5;
    const int bn   = blockIdx.x * 128;
    const int bm   = blockIdx.y * 128;
    const int wm   = (wid & 3) * 32;
    const int wn   = (wid >> 2) * 64;

    const int gRow  = tid >> 1;
    const int half_ = tid & 1;
    const bool aValid = (bm + gRow) < M;
    const float* Ap = A + (size_t)(bm + gRow) * K + half_ * 16;
    const __half* BHp = BHi + (size_t)(bn + gRow) * K + half_ * 16;
    const __half* BLp = BLo + (size_t)(bn + gRow) * K + half_ * 16;
    const uint32_t stsOff = (uint32_t)gRow * (BKP * 2) + half_ * 32;

    const uint32_t aOff = (uint32_t)(wm + (lane & 15)) * (BKP * 2) + ((lane >> 4) << 4);
    const uint32_t bOff = (uint32_t)(wn + (lane & 7) + ((lane >> 4) & 1) * 8) * (BKP * 2)
                        + (((lane >> 3) & 1) << 4);

    float acc[2][8][4];
    #pragma unroll
    for (int mt = 0; mt < 2; mt++)
        #pragma unroll
        for (int nt = 0; nt < 8; nt++)
            #pragma unroll
            for (int j = 0; j < 4; j++) acc[mt][nt][j] = 0.0f;

    constexpr int KT = K / 32;

    float4 aReg[4];
    auto loadA = [&](int kt) {
        #pragma unroll
        for (int i = 0; i < 4; i++) {
            float4 t = aValid ? *(const float4*)(Ap + kt * 32 + 4 * i)
                              : make_float4(0.f, 0.f, 0.f, 0.f);
            if constexpr (FUSE) {
                float4 bb = *(const float4*)(bias + kt * 32 + half_ * 16 + 4 * i);
                t.x = fmaxf(t.x + bb.x, 0.f); t.y = fmaxf(t.y + bb.y, 0.f);
                t.z = fmaxf(t.z + bb.z, 0.f); t.w = fmaxf(t.w + bb.w, 0.f);
                if (!aValid) t = make_float4(0.f, 0.f, 0.f, 0.f);
            }
            aReg[i] = t;
        }
    };
    auto stsA = [&](uint32_t stage) {
        uint32_t hw[8];
        #pragma unroll
        for (int i = 0; i < 4; i++) {
            float4 v = aReg[i];
            __half2 h0; h0.x = __float2half_rn(v.x); h0.y = __float2half_rn(v.y);
            __half2 h1; h1.x = __float2half_rn(v.z); h1.y = __float2half_rn(v.w);
            hw[2 * i]     = *(uint32_t*)&h0;
            hw[2 * i + 1] = *(uint32_t*)&h1;
        }
        uint32_t d = stage + OFF_AHI + stsOff;
        asm volatile("st.shared.v4.b32 [%0], {%1,%2,%3,%4};"
                     :: "r"(d), "r"(hw[0]), "r"(hw[1]), "r"(hw[2]), "r"(hw[3]) : "memory");
        asm volatile("st.shared.v4.b32 [%0], {%1,%2,%3,%4};"
                     :: "r"(d + 16), "r"(hw[4]), "r"(hw[5]), "r"(hw[6]), "r"(hw[7]) : "memory");
    };
    auto cpB = [&](int kt, uint32_t stage) {
        cpasync16(stage + OFF_BHI + stsOff,      BHp + kt * 32);
        cpasync16(stage + OFF_BHI + stsOff + 16, BHp + kt * 32 + 8);
        cpasync16(stage + OFF_BLO + stsOff,      BLp + kt * 32);
        cpasync16(stage + OFF_BLO + stsOff + 16, BLp + kt * 32 + 8);
        asm volatile("cp.async.commit_group;" ::: "memory");
    };

    loadA(0);
    cpB(0, sb);
    stsA(sb);

    for (int kt = 0; kt < KT; kt++) {
        const uint32_t cur = sb + (kt & 1) * ST_BYTES;
        const uint32_t nxt = sb + ((kt + 1) & 1) * ST_BYTES;

        if (kt + 1 < KT) loadA(kt + 1);          // LDG in flight across the wait+mma

        asm volatile("cp.async.wait_group 0;" ::: "memory");
        __syncthreads();

        if (kt + 1 < KT) cpB(kt + 1, nxt);       // async into the freed stage

        #pragma unroll
        for (int kk = 0; kk < 2; kk++) {
            const uint32_t ko = kk * 32;
            uint32_t afh[2][4];
            #pragma unroll
            for (int mt = 0; mt < 2; mt++)
                ldsm4(afh[mt], cur + OFF_AHI + aOff + mt * (16 * BKP * 2) + ko);
            #pragma unroll
            for (int np = 0; np < 4; np++) {
                uint32_t bfh[4], bfl[4];
                ldsm4(bfh, cur + OFF_BHI + bOff + np * (16 * BKP * 2) + ko);
                ldsm4(bfl, cur + OFF_BLO + bOff + np * (16 * BKP * 2) + ko);
                #pragma unroll
                for (int mt = 0; mt < 2; mt++)
                    #pragma unroll
                    for (int j = 0; j < 2; j++) {
                        const int nt = np * 2 + j;
                        mma16816(acc[mt][nt], afh[mt], &bfh[j * 2]);
                        mma16816(acc[mt][nt], afh[mt], &bfl[j * 2]);
                    }
            }
        }

        if (kt + 1 < KT) stsA(nxt);
    }

    #pragma unroll
    for (int mt = 0; mt < 2; mt++) {
        int r0 = bm + wm + mt * 16 + (lane >> 2);
        int r1 = r0 + 8;
        #pragma unroll
        for (int nt = 0; nt < 8; nt++) {
            int cn = bn + wn + nt * 8 + (lane & 3) * 2;
            if (r0 < M)
                *(float2*)&H[(size_t)r0 * 256 + cn] = make_float2(acc[mt][nt][0], acc[mt][nt][1]);
            if (r1 < M)
                *(float2*)&H[(size_t)r1 * 256 + cn] = make_float2(acc[mt][nt][2], acc[mt][nt][3]);
        }
    }
}

// ---------------- CSR aggregation: warp per dst row, no atomics --------------
__global__ __launch_bounds__(256) void k_agg_csr(const float* __restrict__ h,
                                                 float* __restrict__ a) {
    int r = blockIdx.x * 8 + (threadIdx.x >> 5);
    if (r >= N_NODES) return;
    int lane = threadIdx.x & 31;
    float dr = g_dinv[r];
    float w0 = dr * dr;
    const float4* hr = (const float4*)(h + (size_t)r * 256);
    float4 v0 = hr[lane], v1 = hr[lane + 32];
    float4 a0 = make_float4(v0.x * w0, v0.y * w0, v0.z * w0, v0.w * w0);
    float4 a1 = make_float4(v1.x * w0, v1.y * w0, v1.z * w0, v1.w * w0);
    int beg = g_rowbeg[r], end = beg + g_indeg[r];
    for (int t = beg; t < end; t++) {
        int s = g_csrc[t];
        float w = g_dinv[s] * dr;
        const float4* hs = (const float4*)(h + (size_t)s * 256);
        float4 u0 = hs[lane], u1 = hs[lane + 32];
        a0.x += u0.x * w; a0.y += u0.y * w; a0.z += u0.z * w; a0.w += u0.w * w;
        a1.x += u1.x * w; a1.y += u1.y * w; a1.z += u1.z * w; a1.w += u1.w * w;
    }
    float4* ar = (float4*)(a + (size_t)r * 256);
    ar[lane] = a0;
    ar[lane + 32] = a1;
}

// ---------------- pooling: batch sorted -> binary search per graph -----------
__global__ void k_pool(const float* __restrict__ a, const float* __restrict__ b2,
                       float* __restrict__ out) {
    int g = blockIdx.x;
    __shared__ int sLo, sHi;
    if (threadIdx.x == 0) {
        int lo = 0, hi = N_NODES;
        while (lo < hi) { int mid = (lo + hi) >> 1; if (g_batch[mid] < g) lo = mid + 1; else hi = mid; }
        sLo = lo;
        hi = N_NODES;
        while (lo < hi) { int mid = (lo + hi) >> 1; if (g_batch[mid] < g + 1) lo = mid + 1; else hi = mid; }
        sHi = lo;
    }
    __syncthreads();
    int c = threadIdx.x;
    float sum = 0.0f;
    for (int v = sLo; v < sHi; v++) sum += a[(size_t)v * 256 + c];
    int cnt = sHi - sLo;
    out[(size_t)g * 256 + c] = (cnt > 0) ? (sum / (float)cnt + b2[c]) : 0.0f;
}

// ---------------- launcher ---------------------------------------------------
extern "C" void kernel_launch(void* const* d_in, const int* in_sizes, int n_in,
                              void* d_out, int out_size) {
    const float* x    = (const float*)d_in[0];
    const float* W1   = (const float*)d_in[1];
    const float* b1   = (const float*)d_in[2];
    const float* W2   = (const float*)d_in[3];
    const float* b2   = (const float*)d_in[4];
    const void*  ei   = d_in[5];
    const void*  bat  = d_in[6];
    float* out = (float*)d_out;

    float *ph, *pa;
    __half *pw1h, *pw1l, *pw2h, *pw2l;
    cudaGetSymbolAddress((void**)&ph, g_h);
    cudaGetSymbolAddress((void**)&pa, g_a);
    cudaGetSymbolAddress((void**)&pw1h, g_w1hi);
    cudaGetSymbolAddress((void**)&pw1l, g_w1lo);
    cudaGetSymbolAddress((void**)&pw2h, g_w2hi);
    cudaGetSymbolAddress((void**)&pw2l, g_w2lo);

    cudaFuncSetAttribute(k_gemm_tc<IN_CH, false>,
                         cudaFuncAttributeMaxDynamicSharedMemorySize, SMEM_DYN);
    cudaFuncSetAttribute(k_gemm_tc<HID_CH, true>,
                         cudaFuncAttributeMaxDynamicSharedMemorySize, SMEM_DYN);

    dim3 gemmGrid(2, (N_NODES + 127) / 128);     // N-tile fastest: twins share A in L2

    // launch index 3 = GEMM1 (ncu profiles launch index 3)
    k_detect<<<1, 256>>>((const int*)ei);                                 // 0
    k_wprep<<<((IN_CH + HID_CH) * 256 + 255) / 256, 256>>>(W1, W2);       // 1 (zeros indeg too)
    k_convert_deg<<<(2 * N_EDGES + 255) / 256, 256>>>(ei, bat);           // 2
    k_gemm_tc<IN_CH, false><<<gemmGrid, 256, SMEM_DYN>>>(                 // 3 <- profiled
        x, pw1h, pw1l, nullptr, ph, N_NODES);
    k_alloc<<<(N_NODES + 255) / 256, 256>>>();                            // 4
    k_fill<<<(N_EDGES + 255) / 256, 256>>>();                             // 5
    k_agg_csr<<<(N_NODES + 7) / 8, 256>>>(ph, pa);                        // 6
    k_gemm_tc<HID_CH, true><<<gemmGrid, 256, SMEM_DYN>>>(                 // 7
        pa, pw2h, pw2l, b1, ph, N_NODES);
    k_agg_csr<<<(N_NODES + 7) / 8, 256>>>(ph, pa);                        // 8
    k_pool<<<NUM_GRAPHS, 256>>>(pa, b2, out);                             // 9
}

// round 9
// speedup vs baseline: 2.0721x; 1.0916x over previous
#include <cuda_runtime.h>
#include <cuda_fp16.h>
#include <cstdint>

#define N_NODES   200000
#define N_EDGES   400000
#define IN_CH     768
#define HID_CH    256
#define NUM_GRAPHS 8000

// ---------------- scratch (device globals: no allocations allowed) ----------
__device__ int   g_is64;
__device__ int   g_total;
__device__ int   g_edges[2 * N_EDGES];          // [src(E), dst(E)] as int32
__device__ int   g_batch[N_NODES];
__device__ int   g_indeg[N_NODES];
__device__ int   g_rowbeg[N_NODES];             // CSR range start (arbitrary order)
__device__ int   g_cursor[N_NODES];
__device__ int   g_csrc[N_EDGES];               // CSR-by-dst: src ids
__device__ float g_dinv[N_NODES];               // rsqrt(1 + indeg)
__device__ __half2 g_h[(size_t)N_NODES * 128];  // GEMM output, fp16 (gather-read)
__device__ float g_a[(size_t)N_NODES * 256];    // aggregated output, fp32
__device__ __half g_w1hi[256 * IN_CH];          // W^T fp16 hi/lo splits, [n][k] K-major
__device__ __half g_w1lo[256 * IN_CH];
__device__ __half g_w2hi[256 * HID_CH];
__device__ __half g_w2lo[256 * HID_CH];

// ---------------- setup ------------------------------------------------------
__global__ void k_detect(const int* ei32) {
    __shared__ int any;
    if (threadIdx.x == 0) any = 0;
    __syncthreads();
    int idx = threadIdx.x * 3120 + 1;           // max 795601 < 800000 (safe if int32)
    if (ei32[idx] != 0) any = 1;
    __syncthreads();
    if (threadIdx.x == 0) { g_is64 = (any == 0) ? 1 : 0; g_total = 0; }
}

__global__ void k_wprep(const float* __restrict__ W1, const float* __restrict__ W2) {
    int i = blockIdx.x * blockDim.x + threadIdx.x;
    if (i < N_NODES) g_indeg[i] = 0;
    if (i < IN_CH * 256) {
        int k = i / 256, n = i % 256;
        float w = W1[i];
        __half h = __float2half_rn(w);
        g_w1hi[(size_t)n * IN_CH + k] = h;
        g_w1lo[(size_t)n * IN_CH + k] = __float2half_rn(w - __half2float(h));
    } else {
        int j = i - IN_CH * 256;
        if (j < HID_CH * 256) {
            int k = j / 256, n = j % 256;
            float w = W2[j];
            __half h = __float2half_rn(w);
            g_w2hi[(size_t)n * HID_CH + k] = h;
            g_w2lo[(size_t)n * HID_CH + k] = __float2half_rn(w - __half2float(h));
        }
    }
}

__global__ void k_convert_deg(const void* ei, const void* bat) {
    int i = blockIdx.x * blockDim.x + threadIdx.x;
    bool is64 = (g_is64 != 0);
    if (i < N_NODES) {
        g_batch[i] = is64 ? (int)((const long long*)bat)[i] : ((const int*)bat)[i];
    }
    if (i < 2 * N_EDGES) {
        int v = is64 ? (int)((const long long*)ei)[i] : ((const int*)ei)[i];
        g_edges[i] = v;
        if (i >= N_EDGES) atomicAdd(&g_indeg[v], 1);   // dst half
    }
}

__global__ void k_alloc() {
    int i = blockIdx.x * blockDim.x + threadIdx.x;
    if (i >= N_NODES) return;
    int d = g_indeg[i];
    int beg = atomicAdd(&g_total, d);           // uniform-addr -> REDUX aggregated
    g_rowbeg[i] = beg;
    g_cursor[i] = beg;
    g_dinv[i] = rsqrtf(1.0f + (float)d);
}

__global__ void k_fill() {
    int e = blockIdx.x * blockDim.x + threadIdx.x;
    if (e < N_EDGES) {
        int s = g_edges[e], d = g_edges[N_EDGES + e];
        int pos = atomicAdd(&g_cursor[d], 1);
        g_csrc[pos] = s;
    }
}

// ---------------- GEMM helpers ------------------------------------------------
__device__ __forceinline__ void ldsm4(uint32_t r[4], uint32_t addr) {
    asm volatile("ldmatrix.sync.aligned.m8n8.x4.shared.b16 {%0,%1,%2,%3}, [%4];"
        : "=r"(r[0]), "=r"(r[1]), "=r"(r[2]), "=r"(r[3]) : "r"(addr));
}
__device__ __forceinline__ void mma16816(float c[4], const uint32_t a[4], const uint32_t b[2]) {
    asm volatile(
        "mma.sync.aligned.m16n8k16.row.col.f32.f16.f16.f32 "
        "{%0,%1,%2,%3}, {%4,%5,%6,%7}, {%8,%9}, {%0,%1,%2,%3};"
        : "+f"(c[0]), "+f"(c[1]), "+f"(c[2]), "+f"(c[3])
        : "r"(a[0]), "r"(a[1]), "r"(a[2]), "r"(a[3]), "r"(b[0]), "r"(b[1]));
}
__device__ __forceinline__ void cpasync16(uint32_t dst, const void* src) {
    asm volatile("cp.async.cg.shared.global [%0], [%1], 16;" :: "r"(dst), "l"(src));
}
__device__ __forceinline__ uint32_t smem_u32(const void* p) {
    uint32_t a;
    asm("{ .reg .u64 t; cvta.to.shared.u64 t, %1; cvt.u32.u64 %0, t; }" : "=r"(a) : "l"(p));
    return a;
}

// BM=128, BN=128, BK=32, 256 threads (8 warps: 4M x 2N), 3-stage, 2 CTAs/SM.
// A: single fp16 (rounded). B: fp16 hi+lo split -> 2 mma products. H output fp16.
#define BKP 40                       // padded BK row (fp16): 80B stride
#define OFF_AHI 0
#define OFF_BHI (128 * BKP * 2)      // 10240
#define OFF_BLO (2 * 128 * BKP * 2)  // 20480
#define ST_BYTES (3 * 128 * BKP * 2) // 30720 per stage
#define N_STAGE 3
#define SMEM_DYN (N_STAGE * ST_BYTES) // 92160 (2 CTAs = 184KB <= 228KB)

template<int K, bool FUSE>
__global__ __launch_bounds__(256, 2) void k_gemm_tc(
    const float* __restrict__ A,
    const __half* __restrict__ BHi, const __half* __restrict__ BLo,
    const float* __restrict__ bias, __half2* __restrict__ H, int M)
{
    extern __shared__ __align__(16) char smem[];
    const uint32_t sb = smem_u32(smem);

    const int tid  = threadIdx.x;
    const int lane = tid & 31;
    const int wid  = tid >> 5;
    const int bn   = blockIdx.x * 128;
    const int bm   = blockIdx.y * 128;
    const int wm   = (wid & 3) * 32;
    const int wn   = (wid >> 2) * 64;

    const int gRow  = tid >> 1;
    const int half_ = tid & 1;
    const bool aValid = (bm + gRow) < M;
    const float* Ap = A + (size_t)(bm + gRow) * K + half_ * 16;
    const __half* BHp = BHi + (size_t)(bn + gRow) * K + half_ * 16;
    const __half* BLp = BLo + (size_t)(bn + gRow) * K + half_ * 16;
    const uint32_t stsOff = (uint32_t)gRow * (BKP * 2) + half_ * 32;

    const uint32_t aOff = (uint32_t)(wm + (lane & 15)) * (BKP * 2) + ((lane >> 4) << 4);
    const uint32_t bOff = (uint32_t)(wn + (lane & 7) + ((lane >> 4) & 1) * 8) * (BKP * 2)
                        + (((lane >> 3) & 1) << 4);

    float acc[2][8][4];
    #pragma unroll
    for (int mt = 0; mt < 2; mt++)
        #pragma unroll
        for (int nt = 0; nt < 8; nt++)
            #pragma unroll
            for (int j = 0; j < 4; j++) acc[mt][nt][j] = 0.0f;

    constexpr int KT = K / 32;

    float4 aReg[4];
    auto loadA = [&](int kt) {
        #pragma unroll
        for (int i = 0; i < 4; i++) {
            float4 t = aValid ? *(const float4*)(Ap + kt * 32 + 4 * i)
                              : make_float4(0.f, 0.f, 0.f, 0.f);
            if constexpr (FUSE) {
                float4 bb = *(const float4*)(bias + kt * 32 + half_ * 16 + 4 * i);
                t.x = fmaxf(t.x + bb.x, 0.f); t.y = fmaxf(t.y + bb.y, 0.f);
                t.z = fmaxf(t.z + bb.z, 0.f); t.w = fmaxf(t.w + bb.w, 0.f);
                if (!aValid) t = make_float4(0.f, 0.f, 0.f, 0.f);
            }
            aReg[i] = t;
        }
    };
    auto stsA = [&](uint32_t stage) {
        uint32_t hw[8];
        #pragma unroll
        for (int i = 0; i < 4; i++) {
            float4 v = aReg[i];
            __half2 h0; h0.x = __float2half_rn(v.x); h0.y = __float2half_rn(v.y);
            __half2 h1; h1.x = __float2half_rn(v.z); h1.y = __float2half_rn(v.w);
            hw[2 * i]     = *(uint32_t*)&h0;
            hw[2 * i + 1] = *(uint32_t*)&h1;
        }
        uint32_t d = stage + OFF_AHI + stsOff;
        asm volatile("st.shared.v4.b32 [%0], {%1,%2,%3,%4};"
                     :: "r"(d), "r"(hw[0]), "r"(hw[1]), "r"(hw[2]), "r"(hw[3]) : "memory");
        asm volatile("st.shared.v4.b32 [%0], {%1,%2,%3,%4};"
                     :: "r"(d + 16), "r"(hw[4]), "r"(hw[5]), "r"(hw[6]), "r"(hw[7]) : "memory");
    };
    auto cpB = [&](int kt, uint32_t stage) {
        cpasync16(stage + OFF_BHI + stsOff,      BHp + kt * 32);
        cpasync16(stage + OFF_BHI + stsOff + 16, BHp + kt * 32 + 8);
        cpasync16(stage + OFF_BLO + stsOff,      BLp + kt * 32);
        cpasync16(stage + OFF_BLO + stsOff + 16, BLp + kt * 32 + 8);
        asm volatile("cp.async.commit_group;" ::: "memory");
    };

    // prologue: stages 0 and 1
    loadA(0); stsA(sb);                  cpB(0, sb);
    loadA(1); stsA(sb + ST_BYTES);       cpB(1, sb + ST_BYTES);

    for (int kt = 0; kt < KT; kt++) {
        const uint32_t cur = sb + (kt % N_STAGE) * ST_BYTES;

        if (kt + 1 < KT)
            asm volatile("cp.async.wait_group 1;" ::: "memory");
        else
            asm volatile("cp.async.wait_group 0;" ::: "memory");
        __syncthreads();

        if (kt + 2 < KT) loadA(kt + 2);      // LDG covered by the mma loop

        #pragma unroll
        for (int kk = 0; kk < 2; kk++) {
            const uint32_t ko = kk * 32;
            uint32_t afh[2][4];
            #pragma unroll
            for (int mt = 0; mt < 2; mt++)
                ldsm4(afh[mt], cur + OFF_AHI + aOff + mt * (16 * BKP * 2) + ko);
            #pragma unroll
            for (int np = 0; np < 4; np++) {
                uint32_t bfh[4], bfl[4];
                ldsm4(bfh, cur + OFF_BHI + bOff + np * (16 * BKP * 2) + ko);
                ldsm4(bfl, cur + OFF_BLO + bOff + np * (16 * BKP * 2) + ko);
                #pragma unroll
                for (int mt = 0; mt < 2; mt++)
                    #pragma unroll
                    for (int j = 0; j < 2; j++) {
                        const int nt = np * 2 + j;
                        mma16816(acc[mt][nt], afh[mt], &bfh[j * 2]);
                        mma16816(acc[mt][nt], afh[mt], &bfl[j * 2]);
                    }
            }
        }

        if (kt + 2 < KT) {                   // stage (kt+2)%3 freed at iter kt-1
            const uint32_t s2 = sb + ((kt + 2) % N_STAGE) * ST_BYTES;
            stsA(s2);
            cpB(kt + 2, s2);
        }
    }

    // epilogue: H fp16 (half2 per col pair)
    #pragma unroll
    for (int mt = 0; mt < 2; mt++) {
        int r0 = bm + wm + mt * 16 + (lane >> 2);
        int r1 = r0 + 8;
        #pragma unroll
        for (int nt = 0; nt < 8; nt++) {
            int cn = bn + wn + nt * 8 + (lane & 3) * 2;   // even
            if (r0 < M) {
                __half2 hv; hv.x = __float2half_rn(acc[mt][nt][0]);
                            hv.y = __float2half_rn(acc[mt][nt][1]);
                H[(size_t)r0 * 128 + (cn >> 1)] = hv;
            }
            if (r1 < M) {
                __half2 hv; hv.x = __float2half_rn(acc[mt][nt][2]);
                            hv.y = __float2half_rn(acc[mt][nt][3]);
                H[(size_t)r1 * 128 + (cn >> 1)] = hv;
            }
        }
    }
}

// ---------------- CSR aggregation: warp per dst row, fp16 gather -------------
__device__ __forceinline__ void h2mac(uint32_t u, float w, float& x, float& y) {
    __half2 hh = *(__half2*)&u;
    float2 f = __half22float2(hh);
    x = fmaf(f.x, w, x); y = fmaf(f.y, w, y);
}

__global__ __launch_bounds__(256) void k_agg_csr(const __half2* __restrict__ h,
                                                 float* __restrict__ a) {
    int r = blockIdx.x * 8 + (threadIdx.x >> 5);
    if (r >= N_NODES) return;
    int lane = threadIdx.x & 31;
    float dr = g_dinv[r];
    float w0 = dr * dr;
    const uint4* hp = (const uint4*)h;           // 16B = 8 halves; 32 uint4 per row
    uint4 v = hp[(size_t)r * 32 + lane];
    float acc[8] = {0, 0, 0, 0, 0, 0, 0, 0};
    h2mac(v.x, w0, acc[0], acc[1]); h2mac(v.y, w0, acc[2], acc[3]);
    h2mac(v.z, w0, acc[4], acc[5]); h2mac(v.w, w0, acc[6], acc[7]);
    int beg = g_rowbeg[r], end = beg + g_indeg[r];
    for (int t = beg; t < end; t++) {
        int s = g_csrc[t];
        float w = g_dinv[s] * dr;
        uint4 u = hp[(size_t)s * 32 + lane];
        h2mac(u.x, w, acc[0], acc[1]); h2mac(u.y, w, acc[2], acc[3]);
        h2mac(u.z, w, acc[4], acc[5]); h2mac(u.w, w, acc[6], acc[7]);
    }
    float* ar = a + (size_t)r * 256 + lane * 8;
    *(float4*)ar       = make_float4(acc[0], acc[1], acc[2], acc[3]);
    *(float4*)(ar + 4) = make_float4(acc[4], acc[5], acc[6], acc[7]);
}

// ---------------- pooling: batch sorted -> binary search per graph -----------
__global__ void k_pool(const float* __restrict__ a, const float* __restrict__ b2,
                       float* __restrict__ out) {
    int g = blockIdx.x;
    __shared__ int sLo, sHi;
    if (threadIdx.x == 0) {
        int lo = 0, hi = N_NODES;
        while (lo < hi) { int mid = (lo + hi) >> 1; if (g_batch[mid] < g) lo = mid + 1; else hi = mid; }
        sLo = lo;
        hi = N_NODES;
        while (lo < hi) { int mid = (lo + hi) >> 1; if (g_batch[mid] < g + 1) lo = mid + 1; else hi = mid; }
        sHi = lo;
    }
    __syncthreads();
    int c = threadIdx.x;
    float sum = 0.0f;
    for (int v = sLo; v < sHi; v++) sum += a[(size_t)v * 256 + c];
    int cnt = sHi - sLo;
    out[(size_t)g * 256 + c] = (cnt > 0) ? (sum / (float)cnt + b2[c]) : 0.0f;
}

// ---------------- launcher ---------------------------------------------------
extern "C" void kernel_launch(void* const* d_in, const int* in_sizes, int n_in,
                              void* d_out, int out_size) {
    const float* x    = (const float*)d_in[0];
    const float* W1   = (const float*)d_in[1];
    const float* b1   = (const float*)d_in[2];
    const float* W2   = (const float*)d_in[3];
    const float* b2   = (const float*)d_in[4];
    const void*  ei   = d_in[5];
    const void*  bat  = d_in[6];
    float* out = (float*)d_out;

    float *pa;
    __half2 *ph;
    __half *pw1h, *pw1l, *pw2h, *pw2l;
    cudaGetSymbolAddress((void**)&ph, g_h);
    cudaGetSymbolAddress((void**)&pa, g_a);
    cudaGetSymbolAddress((void**)&pw1h, g_w1hi);
    cudaGetSymbolAddress((void**)&pw1l, g_w1lo);
    cudaGetSymbolAddress((void**)&pw2h, g_w2hi);
    cudaGetSymbolAddress((void**)&pw2l, g_w2lo);

    cudaFuncSetAttribute(k_gemm_tc<IN_CH, false>,
                         cudaFuncAttributeMaxDynamicSharedMemorySize, SMEM_DYN);
    cudaFuncSetAttribute(k_gemm_tc<HID_CH, true>,
                         cudaFuncAttributeMaxDynamicSharedMemorySize, SMEM_DYN);

    dim3 gemmGrid(2, (N_NODES + 127) / 128);     // N-tile fastest: twins share A in L2

    // launch index 3 = GEMM1 (ncu profiles launch index 3)
    k_detect<<<1, 256>>>((const int*)ei);                                 // 0
    k_wprep<<<((IN_CH + HID_CH) * 256 + 255) / 256, 256>>>(W1, W2);       // 1 (zeros indeg too)
    k_convert_deg<<<(2 * N_EDGES + 255) / 256, 256>>>(ei, bat);           // 2
    k_gemm_tc<IN_CH, false><<<gemmGrid, 256, SMEM_DYN>>>(                 // 3 <- profiled
        x, pw1h, pw1l, nullptr, ph, N_NODES);
    k_alloc<<<(N_NODES + 255) / 256, 256>>>();                            // 4
    k_fill<<<(N_EDGES + 255) / 256, 256>>>();                             // 5
    k_agg_csr<<<(N_NODES + 7) / 8, 256>>>(ph, pa);                        // 6
    k_gemm_tc<HID_CH, true><<<gemmGrid, 256, SMEM_DYN>>>(                 // 7
        pa, pw2h, pw2l, b1, ph, N_NODES);
    k_agg_csr<<<(N_NODES + 7) / 8, 256>>>(ph, pa);                        // 8
    k_pool<<<NUM_GRAPHS, 256>>>(pa, b2, out);                             // 9
}

// round 10
// speedup vs baseline: 2.4836x; 1.1986x over previous
#include <cuda_runtime.h>
#include <cuda_fp16.h>
#include <cstdint>

#define N_NODES   200000
#define N_EDGES   400000
#define IN_CH     768
#define HID_CH    256
#define NUM_GRAPHS 8000

// ---------------- scratch (device globals: no allocations allowed) ----------
__device__ int   g_is64;
__device__ int   g_total;
__device__ int   g_edges[2 * N_EDGES];          // [src(E), dst(E)] as int32
__device__ int   g_batch[N_NODES];
__device__ int   g_indeg[N_NODES];
__device__ int   g_rowbeg[N_NODES];             // CSR range start (arbitrary order)
__device__ int   g_cursor[N_NODES];
__device__ int   g_csrc[N_EDGES];               // CSR-by-dst: src ids
__device__ float g_dinv[N_NODES];               // rsqrt(1 + indeg)
__device__ __half2 g_h[(size_t)N_NODES * 128];  // GEMM output, fp16 (gather-read)
__device__ float g_a[(size_t)N_NODES * 256];    // aggregated output, fp32
__device__ __half g_w1[256 * IN_CH];            // W^T fp16, [n][k] K-major
__device__ __half g_w2[256 * HID_CH];

// ---------------- setup ------------------------------------------------------
__global__ void k_detect(const int* ei32) {
    __shared__ int any;
    if (threadIdx.x == 0) any = 0;
    __syncthreads();
    int idx = threadIdx.x * 3120 + 1;           // max 795601 < 800000 (safe if int32)
    if (ei32[idx] != 0) any = 1;
    __syncthreads();
    if (threadIdx.x == 0) { g_is64 = (any == 0) ? 1 : 0; g_total = 0; }
}

__global__ void k_wprep(const float* __restrict__ W1, const float* __restrict__ W2) {
    int i = blockIdx.x * blockDim.x + threadIdx.x;
    if (i < N_NODES) g_indeg[i] = 0;
    if (i < IN_CH * 256) {
        int k = i / 256, n = i % 256;
        g_w1[(size_t)n * IN_CH + k] = __float2half_rn(W1[i]);
    } else {
        int j = i - IN_CH * 256;
        if (j < HID_CH * 256) {
            int k = j / 256, n = j % 256;
            g_w2[(size_t)n * HID_CH + k] = __float2half_rn(W2[j]);
        }
    }
}

__global__ void k_convert_deg(const void* ei, const void* bat) {
    int i = blockIdx.x * blockDim.x + threadIdx.x;
    bool is64 = (g_is64 != 0);
    if (i < N_NODES) {
        g_batch[i] = is64 ? (int)((const long long*)bat)[i] : ((const int*)bat)[i];
    }
    if (i < 2 * N_EDGES) {
        int v = is64 ? (int)((const long long*)ei)[i] : ((const int*)ei)[i];
        g_edges[i] = v;
        if (i >= N_EDGES) atomicAdd(&g_indeg[v], 1);   // dst half
    }
}

__global__ void k_alloc() {
    int i = blockIdx.x * blockDim.x + threadIdx.x;
    if (i >= N_NODES) return;
    int d = g_indeg[i];
    int beg = atomicAdd(&g_total, d);           // uniform-addr -> REDUX aggregated
    g_rowbeg[i] = beg;
    g_cursor[i] = beg;
    g_dinv[i] = rsqrtf(1.0f + (float)d);
}

__global__ void k_fill() {
    int e = blockIdx.x * blockDim.x + threadIdx.x;
    if (e < N_EDGES) {
        int s = g_edges[e], d = g_edges[N_EDGES + e];
        int pos = atomicAdd(&g_cursor[d], 1);
        g_csrc[pos] = s;
    }
}

// ---------------- GEMM helpers ------------------------------------------------
__device__ __forceinline__ void ldsm4(uint32_t r[4], uint32_t addr) {
    asm volatile("ldmatrix.sync.aligned.m8n8.x4.shared.b16 {%0,%1,%2,%3}, [%4];"
        : "=r"(r[0]), "=r"(r[1]), "=r"(r[2]), "=r"(r[3]) : "r"(addr));
}
__device__ __forceinline__ void mma16816(float c[4], const uint32_t a[4], const uint32_t b[2]) {
    asm volatile(
        "mma.sync.aligned.m16n8k16.row.col.f32.f16.f16.f32 "
        "{%0,%1,%2,%3}, {%4,%5,%6,%7}, {%8,%9}, {%0,%1,%2,%3};"
        : "+f"(c[0]), "+f"(c[1]), "+f"(c[2]), "+f"(c[3])
        : "r"(a[0]), "r"(a[1]), "r"(a[2]), "r"(a[3]), "r"(b[0]), "r"(b[1]));
}
__device__ __forceinline__ void cpasync16(uint32_t dst, const void* src) {
    asm volatile("cp.async.cg.shared.global [%0], [%1], 16;" :: "r"(dst), "l"(src));
}
__device__ __forceinline__ uint32_t smem_u32(const void* p) {
    uint32_t a;
    asm("{ .reg .u64 t; cvta.to.shared.u64 t, %1; cvt.u32.u64 %0, t; }" : "=r"(a) : "l"(p));
    return a;
}

// BM=128, BN=128, BK=32, 256 threads (8 warps: 4M x 2N), 3-stage, 2 CTAs/SM.
// Single fp16 x fp16 product (A rounded, W rounded), fp32 accum. H output fp16.
#define BKP 40                       // padded BK row (fp16): 80B stride
#define OFF_AHI 0
#define OFF_BHI (128 * BKP * 2)      // 10240
#define ST_BYTES (2 * 128 * BKP * 2) // 20480 per stage
#define N_STAGE 3
#define SMEM_DYN (N_STAGE * ST_BYTES) // 61440 (2 CTAs = 123KB <= 228KB)

template<int K, bool FUSE>
__global__ __launch_bounds__(256, 2) void k_gemm_tc(
    const float* __restrict__ A, const __half* __restrict__ B,
    const float* __restrict__ bias, __half2* __restrict__ H, int M)
{
    extern __shared__ __align__(16) char smem[];
    const uint32_t sb = smem_u32(smem);

    const int tid  = threadIdx.x;
    const int lane = tid & 31;
    const int wid  = tid >> 5;
    const int bn   = blockIdx.x * 128;
    const int bm   = blockIdx.y * 128;
    const int wm   = (wid & 3) * 32;
    const int wn   = (wid >> 2) * 64;

    const int gRow  = tid >> 1;
    const int half_ = tid & 1;
    const bool aValid = (bm + gRow) < M;
    const float* Ap = A + (size_t)(bm + gRow) * K + half_ * 16;
    const __half* Bp = B + (size_t)(bn + gRow) * K + half_ * 16;
    const uint32_t stsOff = (uint32_t)gRow * (BKP * 2) + half_ * 32;

    const uint32_t aOff = (uint32_t)(wm + (lane & 15)) * (BKP * 2) + ((lane >> 4) << 4);
    const uint32_t bOff = (uint32_t)(wn + (lane & 7) + ((lane >> 4) & 1) * 8) * (BKP * 2)
                        + (((lane >> 3) & 1) << 4);

    float acc[2][8][4];
    #pragma unroll
    for (int mt = 0; mt < 2; mt++)
        #pragma unroll
        for (int nt = 0; nt < 8; nt++)
            #pragma unroll
            for (int j = 0; j < 4; j++) acc[mt][nt][j] = 0.0f;

    constexpr int KT = K / 32;

    float4 aReg[4];
    auto loadA = [&](int kt) {
        #pragma unroll
        for (int i = 0; i < 4; i++) {
            float4 t = aValid ? *(const float4*)(Ap + kt * 32 + 4 * i)
                              : make_float4(0.f, 0.f, 0.f, 0.f);
            if constexpr (FUSE) {
                float4 bb = *(const float4*)(bias + kt * 32 + half_ * 16 + 4 * i);
                t.x = fmaxf(t.x + bb.x, 0.f); t.y = fmaxf(t.y + bb.y, 0.f);
                t.z = fmaxf(t.z + bb.z, 0.f); t.w = fmaxf(t.w + bb.w, 0.f);
                if (!aValid) t = make_float4(0.f, 0.f, 0.f, 0.f);
            }
            aReg[i] = t;
        }
    };
    auto stsA = [&](uint32_t stage) {
        uint32_t hw[8];
        #pragma unroll
        for (int i = 0; i < 4; i++) {
            float4 v = aReg[i];
            __half2 h0; h0.x = __float2half_rn(v.x); h0.y = __float2half_rn(v.y);
            __half2 h1; h1.x = __float2half_rn(v.z); h1.y = __float2half_rn(v.w);
            hw[2 * i]     = *(uint32_t*)&h0;
            hw[2 * i + 1] = *(uint32_t*)&h1;
        }
        uint32_t d = stage + OFF_AHI + stsOff;
        asm volatile("st.shared.v4.b32 [%0], {%1,%2,%3,%4};"
                     :: "r"(d), "r"(hw[0]), "r"(hw[1]), "r"(hw[2]), "r"(hw[3]) : "memory");
        asm volatile("st.shared.v4.b32 [%0], {%1,%2,%3,%4};"
                     :: "r"(d + 16), "r"(hw[4]), "r"(hw[5]), "r"(hw[6]), "r"(hw[7]) : "memory");
    };
    auto cpB = [&](int kt, uint32_t stage) {
        cpasync16(stage + OFF_BHI + stsOff,      Bp + kt * 32);
        cpasync16(stage + OFF_BHI + stsOff + 16, Bp + kt * 32 + 8);
        asm volatile("cp.async.commit_group;" ::: "memory");
    };

    // prologue: stages 0 and 1
    loadA(0); stsA(sb);                  cpB(0, sb);
    loadA(1); stsA(sb + ST_BYTES);       cpB(1, sb + ST_BYTES);

    for (int kt = 0; kt < KT; kt++) {
        const uint32_t cur = sb + (kt % N_STAGE) * ST_BYTES;

        if (kt + 1 < KT)
            asm volatile("cp.async.wait_group 1;" ::: "memory");
        else
            asm volatile("cp.async.wait_group 0;" ::: "memory");
        __syncthreads();

        if (kt + 2 < KT) loadA(kt + 2);      // LDG covered by the mma loop

        #pragma unroll
        for (int kk = 0; kk < 2; kk++) {
            const uint32_t ko = kk * 32;
            uint32_t afh[2][4];
            #pragma unroll
            for (int mt = 0; mt < 2; mt++)
                ldsm4(afh[mt], cur + OFF_AHI + aOff + mt * (16 * BKP * 2) + ko);
            #pragma unroll
            for (int np = 0; np < 4; np++) {
                uint32_t bfh[4];
                ldsm4(bfh, cur + OFF_BHI + bOff + np * (16 * BKP * 2) + ko);
                #pragma unroll
                for (int mt = 0; mt < 2; mt++)
                    #pragma unroll
                    for (int j = 0; j < 2; j++)
                        mma16816(acc[mt][np * 2 + j], afh[mt], &bfh[j * 2]);
            }
        }

        if (kt + 2 < KT) {                   // stage (kt+2)%3 freed at iter kt-1
            const uint32_t s2 = sb + ((kt + 2) % N_STAGE) * ST_BYTES;
            stsA(s2);
            cpB(kt + 2, s2);
        }
    }

    // epilogue: H fp16 (half2 per col pair)
    #pragma unroll
    for (int mt = 0; mt < 2; mt++) {
        int r0 = bm + wm + mt * 16 + (lane >> 2);
        int r1 = r0 + 8;
        #pragma unroll
        for (int nt = 0; nt < 8; nt++) {
            int cn = bn + wn + nt * 8 + (lane & 3) * 2;   // even
            if (r0 < M) {
                __half2 hv; hv.x = __float2half_rn(acc[mt][nt][0]);
                            hv.y = __float2half_rn(acc[mt][nt][1]);
                H[(size_t)r0 * 128 + (cn >> 1)] = hv;
            }
            if (r1 < M) {
                __half2 hv; hv.x = __float2half_rn(acc[mt][nt][2]);
                            hv.y = __float2half_rn(acc[mt][nt][3]);
                H[(size_t)r1 * 128 + (cn >> 1)] = hv;
            }
        }
    }
}

// ---------------- CSR aggregation: warp per dst row, fp16 gather -------------
__device__ __forceinline__ void h2mac(uint32_t u, float w, float& x, float& y) {
    __half2 hh = *(__half2*)&u;
    float2 f = __half22float2(hh);
    x = fmaf(f.x, w, x); y = fmaf(f.y, w, y);
}

__global__ __launch_bounds__(256) void k_agg_csr(const __half2* __restrict__ h,
                                                 float* __restrict__ a) {
    int r = blockIdx.x * 8 + (threadIdx.x >> 5);
    if (r >= N_NODES) return;
    int lane = threadIdx.x & 31;
    float dr = g_dinv[r];
    float w0 = dr * dr;
    const uint4* hp = (const uint4*)h;           // 16B = 8 halves; 32 uint4 per row
    uint4 v = hp[(size_t)r * 32 + lane];
    float acc[8] = {0, 0, 0, 0, 0, 0, 0, 0};
    h2mac(v.x, w0, acc[0], acc[1]); h2mac(v.y, w0, acc[2], acc[3]);
    h2mac(v.z, w0, acc[4], acc[5]); h2mac(v.w, w0, acc[6], acc[7]);
    int beg = g_rowbeg[r], end = beg + g_indeg[r];
    for (int t = beg; t < end; t++) {
        int s = g_csrc[t];
        float w = g_dinv[s] * dr;
        uint4 u = hp[(size_t)s * 32 + lane];
        h2mac(u.x, w, acc[0], acc[1]); h2mac(u.y, w, acc[2], acc[3]);
        h2mac(u.z, w, acc[4], acc[5]); h2mac(u.w, w, acc[6], acc[7]);
    }
    float* ar = a + (size_t)r * 256 + lane * 8;
    *(float4*)ar       = make_float4(acc[0], acc[1], acc[2], acc[3]);
    *(float4*)(ar + 4) = make_float4(acc[4], acc[5], acc[6], acc[7]);
}

// ---------------- pooling: batch sorted -> binary search per graph -----------
__global__ void k_pool(const float* __restrict__ a, const float* __restrict__ b2,
                       float* __restrict__ out) {
    int g = blockIdx.x;
    __shared__ int sLo, sHi;
    if (threadIdx.x == 0) {
        int lo = 0, hi = N_NODES;
        while (lo < hi) { int mid = (lo + hi) >> 1; if (g_batch[mid] < g) lo = mid + 1; else hi = mid; }
        sLo = lo;
        hi = N_NODES;
        while (lo < hi) { int mid = (lo + hi) >> 1; if (g_batch[mid] < g + 1) lo = mid + 1; else hi = mid; }
        sHi = lo;
    }
    __syncthreads();
    int c = threadIdx.x;
    float sum = 0.0f;
    for (int v = sLo; v < sHi; v++) sum += a[(size_t)v * 256 + c];
    int cnt = sHi - sLo;
    out[(size_t)g * 256 + c] = (cnt > 0) ? (sum / (float)cnt + b2[c]) : 0.0f;
}

// ---------------- launcher ---------------------------------------------------
extern "C" void kernel_launch(void* const* d_in, const int* in_sizes, int n_in,
                              void* d_out, int out_size) {
    const float* x    = (const float*)d_in[0];
    const float* W1   = (const float*)d_in[1];
    const float* b1   = (const float*)d_in[2];
    const float* W2   = (const float*)d_in[3];
    const float* b2   = (const float*)d_in[4];
    const void*  ei   = d_in[5];
    const void*  bat  = d_in[6];
    float* out = (float*)d_out;

    float *pa;
    __half2 *ph;
    __half *pw1, *pw2;
    cudaGetSymbolAddress((void**)&ph, g_h);
    cudaGetSymbolAddress((void**)&pa, g_a);
    cudaGetSymbolAddress((void**)&pw1, g_w1);
    cudaGetSymbolAddress((void**)&pw2, g_w2);

    cudaFuncSetAttribute(k_gemm_tc<IN_CH, false>,
                         cudaFuncAttributeMaxDynamicSharedMemorySize, SMEM_DYN);
    cudaFuncSetAttribute(k_gemm_tc<HID_CH, true>,
                         cudaFuncAttributeMaxDynamicSharedMemorySize, SMEM_DYN);

    dim3 gemmGrid(2, (N_NODES + 127) / 128);     // N-tile fastest: twins share A in L2

    // launch index 3 = GEMM1 (ncu profiles launch index 3)
    k_detect<<<1, 256>>>((const int*)ei);                                 // 0
    k_wprep<<<((IN_CH + HID_CH) * 256 + 255) / 256, 256>>>(W1, W2);       // 1 (zeros indeg too)
    k_convert_deg<<<(2 * N_EDGES + 255) / 256, 256>>>(ei, bat);           // 2
    k_gemm_tc<IN_CH, false><<<gemmGrid, 256, SMEM_DYN>>>(                 // 3 <- profiled
        x, pw1, nullptr, ph, N_NODES);
    k_alloc<<<(N_NODES + 255) / 256, 256>>>();                            // 4
    k_fill<<<(N_EDGES + 255) / 256, 256>>>();                             // 5
    k_agg_csr<<<(N_NODES + 7) / 8, 256>>>(ph, pa);                        // 6
    k_gemm_tc<HID_CH, true><<<gemmGrid, 256, SMEM_DYN>>>(                 // 7
        pa, pw2, b1, ph, N_NODES);
    k_agg_csr<<<(N_NODES + 7) / 8, 256>>>(ph, pa);                        // 8
    k_pool<<<NUM_GRAPHS, 256>>>(pa, b2, out);                             // 9
}